// round 9
// baseline (speedup 1.0000x reference)
#include <cuda_runtime.h>
#include <cstdint>

#define NB      128
#define CG      4              // block-columns per CTA
#define GROUPS  (NB / CG)      // 32
#define GCOLS   (CG * 32)      // 128
#define NTHR    256
#define MAXL    320
#define N_DIM   4096
#define BATCH   1024
#define NBLKS   4096

// SMEM layout (bytes, from dynamic base)
#define XS_STRIDE  36          // floats per x row (frag loads conflict-free)
#define XS_SLOT    (128 * XS_STRIDE * 4)   // 18432
#define BR_PITCH   40          // floats per raw-B row
#define BR_SLOT    (32 * BR_PITCH * 4)     // 5120
// Paired tf32 B: pr = kt*4+kq (16 rows), float2 slot [pr][n] = {B[k][n], B[k+4][n]},
// k = (pr>>2)*8 + (pr&3).  PITCH must be >= 32 float2 (capacity!) and
// PITCH mod 16 == 4 for conflict-free LDS.64 frag reads -> 36.
#define BP_PITCH   36
#define BP_SLOT    (16 * BP_PITCH * 8)     // 4608
#define XS_OFF     0u
#define BR_OFF     (4u * XS_SLOT)                    // 73728
#define BP_OFF     (BR_OFF + 4u * BR_SLOT)           // 94208
#define LIST_OFF   (BP_OFF + 2u * BP_SLOT)           // 103424
#define BIAS_OFF   (LIST_OFF + 4u * MAXL)            // 104704
#define SMEM_DYN   (BIAS_OFF + 4u * GCOLS)           // 105216

// ---------------- helpers ----------------

__device__ __forceinline__ uint32_t smem_u32(const void* p) {
    uint32_t a;
    asm("{ .reg .u64 t; cvta.to.shared.u64 t, %1; cvt.u32.u64 %0, t; }" : "=r"(a) : "l"(p));
    return a;
}
__device__ __forceinline__ void cpa16(uint32_t dst, const void* src) {
    asm volatile("cp.async.ca.shared.global [%0], [%1], 16;" :: "r"(dst), "l"(src));
}
#define CP_COMMIT() asm volatile("cp.async.commit_group;" ::: "memory")
#define CP_WAIT1()  asm volatile("cp.async.wait_group 1;" ::: "memory")

__device__ __forceinline__ float lds32(uint32_t a) {
    float v;
    asm volatile("ld.shared.f32 %0, [%1];" : "=f"(v) : "r"(a));
    return v;
}
__device__ __forceinline__ void lds64(uint32_t a, uint32_t& r0, uint32_t& r1) {
    asm volatile("ld.shared.v2.b32 {%0,%1}, [%2];" : "=r"(r0), "=r"(r1) : "r"(a));
}
__device__ __forceinline__ float4 lds128(uint32_t a) {
    float4 v;
    asm volatile("ld.shared.v4.f32 {%0,%1,%2,%3}, [%4];"
                 : "=f"(v.x), "=f"(v.y), "=f"(v.z), "=f"(v.w) : "r"(a));
    return v;
}
__device__ __forceinline__ void sts32(uint32_t a, uint32_t v) {
    asm volatile("st.shared.b32 [%0], %1;" :: "r"(a), "r"(v));
}
// cvt.rna.tf32.f32 requires a .b32 destination register -> "=r"
__device__ __forceinline__ uint32_t tf32b(float a) {
    uint32_t r;
    asm("cvt.rna.tf32.f32 %0, %1;" : "=r"(r) : "f"(a));
    return r;
}

#define MMA_TF32(C, A0, A1, A2, A3, B0, B1)                                       \
    asm volatile("mma.sync.aligned.m16n8k8.row.col.f32.tf32.tf32.f32 "            \
                 "{%0,%1,%2,%3},{%4,%5,%6,%7},{%8,%9},{%0,%1,%2,%3};"             \
                 : "+f"((C)[0]), "+f"((C)[1]), "+f"((C)[2]), "+f"((C)[3])         \
                 : "r"(A0), "r"(A1), "r"(A2), "r"(A3), "r"(B0), "r"(B1))

// ---------------- work lists ----------------
// entry: n[0:12) | cib[12:19) | lco[19:21); list preserves sorted (ci,co) order.

__device__ int g_cnt[GROUPS];
__device__ int g_list[GROUPS * MAXL];

__global__ void build_lists_kernel(const int* __restrict__ ci, const int* __restrict__ co) {
    __shared__ int pref[NTHR];
    const int g = blockIdx.x;
    const int t = threadIdx.x;
    const int base = t * (NBLKS / NTHR);   // 16 entries per thread
    int cnt = 0;
#pragma unroll
    for (int j = 0; j < NBLKS / NTHR; j++)
        if ((co[base + j] >> 2) == g) cnt++;
    pref[t] = cnt;
    __syncthreads();
    for (int off = 1; off < NTHR; off <<= 1) {
        int v = (t >= off) ? pref[t - off] : 0;
        __syncthreads();
        pref[t] += v;
        __syncthreads();
    }
    int pos = pref[t] - cnt;
#pragma unroll
    for (int j = 0; j < NBLKS / NTHR; j++) {
        int n = base + j;
        int c = co[n];
        if ((c >> 2) == g) {
            g_list[g * MAXL + pos] = n | (ci[n] << 12) | ((c & 3) << 19);
            pos++;
        }
    }
    if (t == NTHR - 1) g_cnt[g] = pref[NTHR - 1];
}

// ---------------- per-block compute ----------------
// PTX m16n8k8.row.col A layout (row = lane>>2, col = lane&3):
//   a0=(row,col) a1=(row+8,col) a2=(row,col+4) a3=(row+8,col+4)
// B fragment: b0=(k=lane&3, n=lane>>2), b1=(k+4, n) -> one LDS.64 from paired buf.

template <int LCO>
__device__ __forceinline__ void compute_block(float (&acc)[16][4],
                                              const uint32_t (&afr)[4][4],
                                              uint32_t bpb, int kq, int nq) {
#pragma unroll
    for (int kt = 0; kt < 4; kt++) {
        uint32_t rowa = bpb + 8u * ((uint32_t)(kt * 4 + kq) * BP_PITCH + nq);
#pragma unroll
        for (int nt = 0; nt < 4; nt++) {
            uint32_t b0, b1;
            lds64(rowa + 8u * (uint32_t)(nt * 8), b0, b1);
            MMA_TF32(acc[4 * LCO + nt], afr[kt][0], afr[kt][1], afr[kt][2], afr[kt][3], b0, b1);
        }
    }
}

__device__ __forceinline__ void load_afrags(uint32_t (&afr)[4][4], uint32_t xs_warp,
                                            int kq, int nq) {
#pragma unroll
    for (int kt = 0; kt < 4; kt++) {
        uint32_t r0 = xs_warp + 4u * ((uint32_t)nq * XS_STRIDE + kt * 8 + kq);
        afr[kt][0] = tf32b(lds32(r0));                              // (row,   col)
        afr[kt][1] = tf32b(lds32(r0 + 8u * XS_STRIDE * 4u));        // (row+8, col)
        afr[kt][2] = tf32b(lds32(r0 + 16u));                        // (row,   col+4)
        afr[kt][3] = tf32b(lds32(r0 + 8u * XS_STRIDE * 4u + 16u));  // (row+8, col+4)
    }
}

// ---------------- main kernel ----------------

__global__ void __launch_bounds__(NTHR, 2)
bs_mma_kernel(const float* __restrict__ x, const float* __restrict__ kern,
              const float* __restrict__ bias, float* __restrict__ out) {
    extern __shared__ char smem_raw[];
    const uint32_t base = smem_u32(smem_raw);
    int* list_s = (int*)(smem_raw + LIST_OFF);
    float* bias_s = (float*)(smem_raw + BIAS_OFF);

    const int g   = blockIdx.x;
    const int by  = blockIdx.y;
    const int tid = threadIdx.x;
    const int w   = tid >> 5;
    const int lane = tid & 31;
    const int kq  = lane & 3;
    const int nq  = lane >> 2;

    const int cnt = g_cnt[g];
    for (int j = tid; j < cnt; j += NTHR) list_s[j] = g_list[g * MAXL + j];
    if (tid < GCOLS) bias_s[tid] = bias[g * GCOLS + tid];
    __syncthreads();

    float acc[16][4];
#pragma unroll
    for (int i = 0; i < 16; i++)
#pragma unroll
        for (int j = 0; j < 4; j++) acc[i][j] = 0.f;

    const float* xrow0 = x + (size_t)(by * 128) * N_DIM;

    auto stage_x = [&](int cib, int slot) {
        const float* src = xrow0 + cib * 32;
        uint32_t dst = base + XS_OFF + (uint32_t)slot * XS_SLOT;
#pragma unroll
        for (int j = 0; j < 4; j++) {
            int id = tid + j * NTHR;        // 0..1023 float4 slots
            int row = id >> 3, c4 = id & 7;
            cpa16(dst + (uint32_t)row * (XS_STRIDE * 4) + c4 * 16u,
                  src + (size_t)row * N_DIM + c4 * 4);
        }
    };
    // raw B staging: thread owns row k = tid>>3, cols n0..n0+3
    const int bk  = tid >> 3;
    const int bn0 = 4 * (tid & 7);
    auto stage_braw = [&](int n, int slot) {
        cpa16(base + BR_OFF + (uint32_t)slot * BR_SLOT + 4u * ((uint32_t)bk * BR_PITCH + bn0),
              kern + (size_t)n * 1024 + bk * 32 + bn0);
    };
    // convert raw B (slot j&3) -> tf32 paired buffer (slot j&1)
    const int bpr = ((bk >> 3) << 2) | (bk & 3);
    const int be  = (bk >> 2) & 1;
    auto convert_b = [&](int j) {
        float4 v = lds128(base + BR_OFF + (uint32_t)(j & 3) * BR_SLOT +
                          4u * ((uint32_t)bk * BR_PITCH + bn0));
        uint32_t a0 = base + BP_OFF + (uint32_t)(j & 1) * BP_SLOT +
                      8u * ((uint32_t)bpr * BP_PITCH + bn0) + (uint32_t)be * 4u;
        sts32(a0,       tf32b(v.x));
        sts32(a0 + 8u,  tf32b(v.y));
        sts32(a0 + 16u, tf32b(v.z));
        sts32(a0 + 24u, tf32b(v.w));
    };

    if (cnt > 0) {
        int staged_cib = -1, staged_slot = 3;
        int s0 = 0, s1 = 0, s2 = 0;

        auto prefetch = [&](int j) -> int {
            int e = list_s[j];
            int cib = (e >> 12) & 127;
            if (cib != staged_cib) {
                staged_slot = (staged_slot + 1) & 3;
                stage_x(cib, staged_slot);
                staged_cib = cib;
            }
            stage_braw(e & 0xFFF, j & 3);
            return staged_slot;
        };

        s0 = prefetch(0);
        CP_COMMIT();
        if (cnt > 1) s1 = prefetch(1);
        CP_COMMIT();
        CP_WAIT1();          // entry 0 raw arrived
        __syncthreads();
        convert_b(0);        // paired slot 0 ready (visible after iter-0 sync)

        uint32_t afr[4][4];
        int frag_cib = -1;

        for (int i = 0; i < cnt; i++) {
            if (i + 2 < cnt) s2 = prefetch(i + 2);
            CP_COMMIT();
            CP_WAIT1();            // raw for entry i+1 arrived (committed last iter)
            __syncthreads();       // staging + prev convert visible to all

            if (i + 1 < cnt) convert_b(i + 1);

            int vi  = list_s[i];
            int lco = (vi >> 19) & 3;
            int cib_i = (vi >> 12) & 127;

            if (cib_i != frag_cib) {
                load_afrags(afr, base + XS_OFF + (uint32_t)s0 * XS_SLOT +
                                 (uint32_t)(16 * w) * (XS_STRIDE * 4), kq, nq);
                frag_cib = cib_i;
            }

            uint32_t bpb = base + BP_OFF + (uint32_t)(i & 1) * BP_SLOT;
            switch (lco) {
                case 0: compute_block<0>(acc, afr, bpb, kq, nq); break;
                case 1: compute_block<1>(acc, afr, bpb, kq, nq); break;
                case 2: compute_block<2>(acc, afr, bpb, kq, nq); break;
                default: compute_block<3>(acc, afr, bpb, kq, nq); break;
            }

            s0 = s1; s1 = s2;
        }
    }

    // ---- epilogue: bias + relu ----
    {
        int r = 16 * w + nq;
        size_t rb0 = (size_t)(by * 128 + r) * N_DIM + g * GCOLS;
        size_t rb1 = rb0 + 8 * (size_t)N_DIM;
#pragma unroll
        for (int nt = 0; nt < 16; nt++) {
            int c = nt * 8 + 2 * kq;
            float b0 = bias_s[c], b1 = bias_s[c + 1];
            float2 v0, v1;
            v0.x = fmaxf(acc[nt][0] + b0, 0.f);
            v0.y = fmaxf(acc[nt][1] + b1, 0.f);
            v1.x = fmaxf(acc[nt][2] + b0, 0.f);
            v1.y = fmaxf(acc[nt][3] + b1, 0.f);
            *(float2*)(out + rb0 + c) = v0;
            *(float2*)(out + rb1 + c) = v1;
        }
    }
}

extern "C" void kernel_launch(void* const* d_in, const int* in_sizes, int n_in,
                              void* d_out, int out_size) {
    const float* x    = (const float*)d_in[0];
    const float* kern = (const float*)d_in[1];
    const float* bias = (const float*)d_in[2];
    const int*   ci   = (const int*)d_in[3];
    const int*   co   = (const int*)d_in[4];
    float* out = (float*)d_out;

    cudaFuncSetAttribute(bs_mma_kernel, cudaFuncAttributeMaxDynamicSharedMemorySize, SMEM_DYN);

    build_lists_kernel<<<GROUPS, NTHR>>>(ci, co);
    dim3 grid(GROUPS, BATCH / 128);
    bs_mma_kernel<<<grid, NTHR, SMEM_DYN>>>(x, kern, bias, out);
}